// round 17
// baseline (speedup 1.0000x reference)
#include <cuda_runtime.h>
#include <cuda_bf16.h>

#define B_ 64
#define T_ 1024
#define I_ 8
#define H_ 512
#define O_ 2
#define NOISE_STD_ 0.05f
#define ALPHA_ 0.2f

#define NT_    192          // w2=consumer-A(SMSP2), w3=consumer-B(SMSP3), w0/w1/w4/w5=producers
#define RING_  16           // e-ring slots (32 KB)

#define SA_      8192.0f    // 2^13 scale for recurrence dots
#define SO_      2097152.0f // 2^21 scale for output dots
#define MAGIC_F  12582912.0f        // 2^23 + 2^22 round-to-int bias
// Each warp's REDUX of 32 biased floats carries bias 32*0x4B400000 = 0x68000000 (mod 2^32).
// TWO warps combined: 0xD0000000 + S. Re-bias: + (0x4B400000 - 0xD0000000) = 0x7B400000.
#define REBIAS2_I ((int)0x7B400000)

typedef unsigned long long u64;

__device__ __forceinline__ float tanh_mufu(float x) {
    float r; asm("tanh.approx.f32 %0, %1;" : "=f"(r) : "f"(x)); return r;
}
__device__ __forceinline__ int redux_add_s32(int v) {
    int r; asm volatile("redux.sync.add.s32 %0, %1, 0xffffffff;" : "=r"(r) : "r"(v)); return r;
}
// volatile LDS.128 as two packed f32x2 words
__device__ __forceinline__ void ldsu2(const float* p, u64& a, u64& b) {
    unsigned ad = (unsigned)__cvta_generic_to_shared(p);
    asm volatile("ld.volatile.shared.v2.u64 {%0,%1}, [%2];"
                 : "=l"(a), "=l"(b) : "r"(ad));
}
// tagged exchange: single 128-bit volatile st/ld (tag travels atomically with data)
__device__ __forceinline__ void stv4(int4* p, int x, int y, int z, int wv) {
    asm volatile("st.volatile.v4.b32 [%0], {%1,%2,%3,%4};"
                 :: "l"(p), "r"(x), "r"(y), "r"(z), "r"(wv) : "memory");
}
__device__ __forceinline__ int4 ldv4(const int4* p) {
    int4 v;
    asm volatile("ld.volatile.v4.b32 {%0,%1,%2,%3}, [%4];"
                 : "=r"(v.x), "=r"(v.y), "=r"(v.z), "=r"(v.w) : "l"(p) : "memory");
    return v;
}
// ---- packed f32x2 (PTX-only on sm_103a) ----
__device__ __forceinline__ u64 pack2(float x, float y) {
    u64 r; asm("mov.b64 %0, {%1, %2};" : "=l"(r) : "f"(x), "f"(y)); return r;
}
__device__ __forceinline__ void unpack2(u64 v, float& x, float& y) {
    asm("mov.b64 {%0, %1}, %2;" : "=f"(x), "=f"(y) : "l"(v));
}
__device__ __forceinline__ u64 fma2(u64 a, u64 b, u64 c) {
    u64 r; asm("fma.rn.f32x2 %0, %1, %2, %3;" : "=l"(r) : "l"(a), "l"(b), "l"(c)); return r;
}
__device__ __forceinline__ u64 mul2(u64 a, u64 b) {
    u64 r; asm("mul.rn.f32x2 %0, %1, %2;" : "=l"(r) : "l"(a), "l"(b)); return r;
}
__device__ __forceinline__ u64 add2(u64 a, u64 b) {
    u64 r; asm("add.rn.f32x2 %0, %1, %2;" : "=l"(r) : "l"(a), "l"(b)); return r;
}

__global__ __launch_bounds__(NT_, 1)
void lowrank_rnn_kernel(const float* __restrict__ input,   // (B,T,I)
                        const float* __restrict__ noise,   // (B,T,H)
                        const float* __restrict__ wi,      // (I,H)
                        const float* __restrict__ si,      // (I,)
                        const float* __restrict__ m,       // (H,R)
                        const float* __restrict__ n,       // (H,R)
                        const float* __restrict__ wo,      // (H,O)
                        const float* __restrict__ so,      // (O,)
                        const float* __restrict__ h0,      // (H,)
                        float* __restrict__ out,           // (B,T,O)
                        float* __restrict__ traj)          // (B,T,H)
{
    __shared__ float s_e[RING_][H_];       // e(t) = 0.05nz + alpha*proj + negmc
    __shared__ int4  s_xa[2][4];           // [half][slot]: (ia0, ia1, 0, tag) a-exchange
    __shared__ int4  s_xb[2][4];           // [half][slot]: (io0, io1, tag, 0) o-exchange
    __shared__ int2  s_pro[2];             // prologue a-partials
    __shared__ volatile int s_pcnt[4];     // producers: e ready through step pcnt-1
    __shared__ volatile int s_ccnt;        // consumer-A progress (gates producers)

    const int b    = blockIdx.x;
    const int tid  = threadIdx.x;
    const int w    = tid >> 5;
    const int lane = tid & 31;

    const float cm = (ALPHA_ / (float)H_) / SA_;   // alpha/H and 1/Sa folded into m

    if (w != 2 && w != 3) {
        // =================== PRODUCER (warps 0,1,4,5 on SMSP0/1) ===================
        const int pw = (w < 2) ? w : w - 2;        // 0..3
        const int k0 = (pw * 32 + lane) * 4;

        float wif[I_][4];                          // wi * si * alpha
        #pragma unroll
        for (int i = 0; i < I_; ++i) {
            const float4 ww = *(const float4*)(wi + i * H_ + k0);
            const float  s  = si[i] * ALPHA_;
            wif[i][0] = ww.x * s; wif[i][1] = ww.y * s;
            wif[i][2] = ww.z * s; wif[i][3] = ww.w * s;
        }
        float negmc[4];                            // -MAGIC*(m0f+m1f), folded into e
        {
            const float4 mA = *(const float4*)(m + k0 * 2);
            const float4 mB = *(const float4*)(m + k0 * 2 + 4);
            negmc[0] = -MAGIC_F * (mA.x * cm + mA.y * cm);
            negmc[1] = -MAGIC_F * (mA.z * cm + mA.w * cm);
            negmc[2] = -MAGIC_F * (mB.x * cm + mB.y * cm);
            negmc[3] = -MAGIC_F * (mB.z * cm + mB.w * cm);
        }
        const float* nz_base = noise + (size_t)b * T_ * H_ + k0;
        const float* in_base = input + (size_t)b * T_ * I_;

        if (tid == 0) s_ccnt = 0;
        for (int s = 0; s < 8; ++s) {              // prologue: steps 0..7
            const float4 nz = *(const float4*)(nz_base + (size_t)s * H_);
            const float4 x0 = __ldg((const float4*)(in_base + s * I_));
            const float4 x1 = __ldg((const float4*)(in_base + s * I_ + 4));
            const float nza[4] = {nz.x, nz.y, nz.z, nz.w};
            float e[4];
            #pragma unroll
            for (int u = 0; u < 4; ++u) {
                float pp = fmaf(NOISE_STD_, nza[u], negmc[u]);
                pp = fmaf(x0.x, wif[0][u], pp);
                pp = fmaf(x0.y, wif[1][u], pp);
                pp = fmaf(x0.z, wif[2][u], pp);
                pp = fmaf(x0.w, wif[3][u], pp);
                pp = fmaf(x1.x, wif[4][u], pp);
                pp = fmaf(x1.y, wif[5][u], pp);
                pp = fmaf(x1.z, wif[6][u], pp);
                pp = fmaf(x1.w, wif[7][u], pp);
                e[u] = pp;
            }
            *(float4*)&s_e[s][k0] = make_float4(e[0], e[1], e[2], e[3]);
        }
        if (lane == 0) s_pcnt[pw] = 8;
        float4 rnz[4], rx0[4], rx1[4];
        #pragma unroll
        for (int j = 0; j < 4; ++j) {
            const int t = 8 + j;
            rnz[j] = *(const float4*)(nz_base + (size_t)t * H_);
            rx0[j] = __ldg((const float4*)(in_base + t * I_));
            rx1[j] = __ldg((const float4*)(in_base + t * I_ + 4));
        }
        __syncthreads();

        int ccached = 0;
        #pragma unroll 4
        for (int tp = 8; tp < T_; ++tp) {
            // B may lag A by 1 step: guard with +11 (ring 16)
            if (tp > ccached + 11) {
                ccached = s_ccnt;
                while (tp > ccached + 11) { __nanosleep(200); ccached = s_ccnt; }
            }
            const int j = tp & 3;
            const float4 nz = rnz[j];
            const float4 x0 = rx0[j];
            const float4 x1 = rx1[j];
            int tl = tp + 4; if (tl > T_ - 1) tl = T_ - 1;
            rnz[j] = *(const float4*)(nz_base + (size_t)tl * H_);
            rx0[j] = __ldg((const float4*)(in_base + tl * I_));
            rx1[j] = __ldg((const float4*)(in_base + tl * I_ + 4));

            const float nza[4] = {nz.x, nz.y, nz.z, nz.w};
            float e[4];
            #pragma unroll
            for (int u = 0; u < 4; ++u) {
                float pp = fmaf(NOISE_STD_, nza[u], negmc[u]);
                pp = fmaf(x0.x, wif[0][u], pp);
                pp = fmaf(x0.y, wif[1][u], pp);
                pp = fmaf(x0.z, wif[2][u], pp);
                pp = fmaf(x0.w, wif[3][u], pp);
                pp = fmaf(x1.x, wif[4][u], pp);
                pp = fmaf(x1.y, wif[5][u], pp);
                pp = fmaf(x1.z, wif[6][u], pp);
                pp = fmaf(x1.w, wif[7][u], pp);
                e[u] = pp;
            }
            *(float4*)&s_e[tp & (RING_ - 1)][k0] = make_float4(e[0], e[1], e[2], e[3]);

            if ((tp & 3) == 3) {
                __threadfence_block();
                if (lane == 0) s_pcnt[pw] = tp + 1;
            }
        }
    } else {
        // ========= CONSUMER pair: w2 = half 0 (units 0-255), w3 = half 1 (256-511) =========
        const int half  = w - 2;
        const int other = 1 - half;

        const float so0 = (so[0] / (float)H_) * SO_;
        const float so1 = (so[1] / (float)H_) * SO_;
        u64 m0f2[4], m1f2[4], n0f2[4], n1f2[4], wo0f2[4], wo1f2[4], h2[4];
        #pragma unroll
        for (int jb = 0; jb < 2; ++jb) {
            const int k0 = half * 256 + jb * 128 + lane * 4;
            const float4 mA = *(const float4*)(m + k0 * 2);
            const float4 mB = *(const float4*)(m + k0 * 2 + 4);
            const float4 nA = *(const float4*)(n + k0 * 2);
            const float4 nB = *(const float4*)(n + k0 * 2 + 4);
            const float4 wA = *(const float4*)(wo + k0 * 2);
            const float4 wB = *(const float4*)(wo + k0 * 2 + 4);
            const float4 hh = *(const float4*)(h0 + k0);
            const int p = jb * 2;
            m0f2[p]    = pack2(mA.x * cm,  mA.z * cm);
            m1f2[p]    = pack2(mA.y * cm,  mA.w * cm);
            m0f2[p+1]  = pack2(mB.x * cm,  mB.z * cm);
            m1f2[p+1]  = pack2(mB.y * cm,  mB.w * cm);
            n0f2[p]    = pack2(nA.x * SA_, nA.z * SA_);
            n1f2[p]    = pack2(nA.y * SA_, nA.w * SA_);
            n0f2[p+1]  = pack2(nB.x * SA_, nB.z * SA_);
            n1f2[p+1]  = pack2(nB.y * SA_, nB.w * SA_);
            wo0f2[p]   = pack2(wA.x * so0, wA.z * so0);
            wo1f2[p]   = pack2(wA.y * so1, wA.w * so1);
            wo0f2[p+1] = pack2(wB.x * so0, wB.z * so0);
            wo1f2[p+1] = pack2(wB.y * so1, wB.w * so1);
            h2[p]      = pack2(hh.x, hh.y);
            h2[p+1]    = pack2(hh.z, hh.w);
        }
        const u64 C08 = pack2(1.0f - ALPHA_, 1.0f - ALPHA_);
        float* traj_base = traj + (size_t)b * T_ * H_ + half * 256 + lane * 4;
        float* out_base  = out  + (size_t)b * T_ * O_;

        // init exchange tags (fresh every launch / graph replay)
        if (lane == 0) {
            #pragma unroll
            for (int s = 0; s < 4; ++s) {
                stv4(&s_xa[half][s], 0, 0, 0, -1);
                stv4(&s_xb[half][s], 0, 0, -1, 0);
            }
        }

        // prologue: a(0) via barrier-ordered exchange
        float A0b, A1b;
        {
            u64 acc0 = 0, acc1 = 0;
            #pragma unroll
            for (int p = 0; p < 4; ++p) {
                float xl, xh; unpack2(h2[p], xl, xh);
                const u64 r2 = pack2(tanh_mufu(xl), tanh_mufu(xh));
                if (p == 0) { acc0 = mul2(r2, n0f2[p]); acc1 = mul2(r2, n1f2[p]); }
                else        { acc0 = fma2(r2, n0f2[p], acc0); acc1 = fma2(r2, n1f2[p], acc1); }
            }
            float a0l, a0h, a1l, a1h;
            unpack2(acc0, a0l, a0h); unpack2(acc1, a1l, a1h);
            const int W0 = redux_add_s32(__float_as_int((a0l + a0h) + MAGIC_F));
            const int W1 = redux_add_s32(__float_as_int((a1l + a1h) + MAGIC_F));
            if (lane == 0) s_pro[half] = make_int2(W0, W1);
            __syncthreads();                       // also orders tag init + e prologue
            const int2 ov = s_pro[other];
            A0b = __int_as_float((W0 + ov.x) + REBIAS2_I);
            A1b = __int_as_float((W1 + ov.y) + REBIAS2_I);
        }

        u64 e2[4];
        #pragma unroll
        for (int jb = 0; jb < 2; ++jb)
            ldsu2(&s_e[0][half * 256 + jb * 128 + lane * 4], e2[jb * 2], e2[jb * 2 + 1]);
        int avail = 8;
        int U0p = 0, U1p = 0;                      // own o-partials from prev step (A only)

        #pragma unroll 2
        for (int t = 0; t < T_; ++t) {
            const u64 A02 = pack2(A0b, A0b);
            const u64 A12 = pack2(A1b, A1b);

            // h(t+1) = 0.8h + e + A0*m0 + A1*m1  (bias cancels via negmc in e)
            #pragma unroll
            for (int p = 0; p < 4; ++p) {
                u64 hb = fma2(C08, h2[p], e2[p]);
                u64 hx = fma2(A02, m0f2[p], hb);
                h2[p]  = fma2(A12, m1f2[p], hx);
            }
            // traj[t]: 2x STG.128
            #pragma unroll
            for (int jb = 0; jb < 2; ++jb) {
                ulonglong2 st;
                st.x = h2[jb * 2]; st.y = h2[jb * 2 + 1];
                *(ulonglong2*)(traj_base + (size_t)t * H_ + jb * 128) = st;
            }
            // tanh (8 MUFU) + a-dots — critical path
            u64 r2v[4];
            #pragma unroll
            for (int p = 0; p < 4; ++p) {
                float xl, xh; unpack2(h2[p], xl, xh);
                r2v[p] = pack2(tanh_mufu(xl), tanh_mufu(xh));
            }
            u64 acc0 = mul2(r2v[0], n0f2[0]);
            u64 acc1 = mul2(r2v[0], n1f2[0]);
            #pragma unroll
            for (int p = 1; p < 4; ++p) {
                acc0 = fma2(r2v[p], n0f2[p], acc0);
                acc1 = fma2(r2v[p], n1f2[p], acc1);
            }
            float a0l, a0h, a1l, a1h;
            unpack2(acc0, a0l, a0h); unpack2(acc1, a1l, a1h);
            const int W0 = redux_add_s32(__float_as_int((a0l + a0h) + MAGIC_F));
            const int W1 = redux_add_s32(__float_as_int((a1l + a1h) + MAGIC_F));
            if (lane == 0) stv4(&s_xa[half][t & 3], W0, W1, 0, t);   // publish a FIRST

            // o-dots (off the a-exchange path)
            u64 ob0 = mul2(r2v[0], wo0f2[0]);
            u64 ob1 = mul2(r2v[0], wo1f2[0]);
            #pragma unroll
            for (int p = 1; p < 4; ++p) {
                ob0 = fma2(r2v[p], wo0f2[p], ob0);
                ob1 = fma2(r2v[p], wo1f2[p], ob1);
            }
            float o0l, o0h, o1l, o1h;
            unpack2(ob0, o0l, o0h); unpack2(ob1, o1l, o1h);
            const int U0 = redux_add_s32(__float2int_rn(o0l + o0h));
            const int U1 = redux_add_s32(__float2int_rn(o1l + o1h));
            if (lane == 0) stv4(&s_xb[half][t & 3], U0, U1, t, 0);

            // e(t+1) prefetch
            int tn = t + 1; if (tn > T_ - 1) tn = T_ - 1;
            if (avail < tn + 1) {
                do {
                    avail = min(min(s_pcnt[0], s_pcnt[1]), min(s_pcnt[2], s_pcnt[3]));
                } while (avail < tn + 1);
            }
            {
                const int slot = tn & (RING_ - 1);
                #pragma unroll
                for (int jb = 0; jb < 2; ++jb)
                    ldsu2(&s_e[slot][half * 256 + jb * 128 + lane * 4],
                          e2[jb * 2], e2[jb * 2 + 1]);
            }

            // poll other's a-entry and combine (int-exact)
            int4 v;
            do { v = ldv4(&s_xa[other][t & 3]); } while (v.w != t);
            A0b = __int_as_float((W0 + v.x) + REBIAS2_I);
            A1b = __int_as_float((W1 + v.y) + REBIAS2_I);

            // out[t-1]: consumer-A lane 0 (lazy, one step behind)
            if (half == 0) {
                if (lane == 0 && t > 0) {
                    int4 vo;
                    do { vo = ldv4(&s_xb[1][(t - 1) & 3]); } while (vo.z != t - 1);
                    const float o0 = (float)(U0p + vo.x) * (1.0f / SO_);
                    const float o1 = (float)(U1p + vo.y) * (1.0f / SO_);
                    *(float2*)(out_base + (size_t)(t - 1) * O_) = make_float2(o0, o1);
                }
                U0p = U0; U1p = U1;
                if ((t & 3) == 3) {                // gate producers
                    __syncwarp();
                    __threadfence_block();
                    if (lane == 0) s_ccnt = t + 1;
                }
            }
        }
        // final out[T-1]
        if (half == 0 && lane == 0) {
            int4 vo;
            do { vo = ldv4(&s_xb[1][(T_ - 1) & 3]); } while (vo.z != T_ - 1);
            const float o0 = (float)(U0p + vo.x) * (1.0f / SO_);
            const float o1 = (float)(U1p + vo.y) * (1.0f / SO_);
            *(float2*)(out_base + (size_t)(T_ - 1) * O_) = make_float2(o0, o1);
        }
    }
}

extern "C" void kernel_launch(void* const* d_in, const int* in_sizes, int n_in,
                              void* d_out, int out_size) {
    const float* input = (const float*)d_in[0];
    const float* noise = (const float*)d_in[1];
    const float* wi    = (const float*)d_in[2];
    const float* si    = (const float*)d_in[3];
    const float* m     = (const float*)d_in[4];
    const float* n     = (const float*)d_in[5];
    const float* wo    = (const float*)d_in[6];
    const float* so    = (const float*)d_in[7];
    const float* h0    = (const float*)d_in[8];

    float* out  = (float*)d_out;                         // (B,T,O) first
    float* traj = (float*)d_out + (size_t)B_ * T_ * O_;  // then (B,T,H)

    lowrank_rnn_kernel<<<B_, NT_>>>(input, noise, wi, si, m, n, wo, so, h0,
                                    out, traj);
}